// round 16
// baseline (speedup 1.0000x reference)
#include <cuda_runtime.h>

#define NB_DIMS 128
#define BATCH   16384

// One warp per sample. Each lane issues ONE 256-bit gather (the only width
// ptxas accepts L2::evict_last on): lanes 0-15 cover row idx.x, lanes 16-31
// cover row idx.y (16 lanes x 32B = 512B row, fully coalesced). evict_last
// keeps the 16.8MB gathered set resident in the 126MB L2 across graph
// replays (hypothesis: warm replays become L2-bound). Cross-row pairing via
// one shfl_xor(16); butterfly reduce within the 16-lane group.
__global__ void __launch_bounds__(256) sgns_dot_kernel(
    const int*   __restrict__ vii,   // [BATCH, 2] int32
    const float* __restrict__ W,     // [NB_VECS, 128] f32
    float*       __restrict__ out)   // [BATCH] f32
{
    int gtid = blockIdx.x * blockDim.x + threadIdx.x;
    int warp = gtid >> 5;            // in [0, BATCH) by construction
    int lane = gtid & 31;

    // Both indices in one broadcast 8B load.
    int2 idx = __ldg(reinterpret_cast<const int2*>(vii) + warp);

    int row = (lane < 16) ? idx.x : idx.y;
    const float* p = W + (long long)row * NB_DIMS + (lane & 15) * 8;

    // 256-bit keep-in-L2 gather: 8 floats per lane.
    unsigned r0, r1, r2, r3, r4, r5, r6, r7;
    asm volatile(
        "ld.global.nc.L2::evict_last.v8.b32 {%0,%1,%2,%3,%4,%5,%6,%7}, [%8];"
        : "=r"(r0), "=r"(r1), "=r"(r2), "=r"(r3),
          "=r"(r4), "=r"(r5), "=r"(r6), "=r"(r7)
        : "l"(p));

    float v0 = __uint_as_float(r0), v1 = __uint_as_float(r1);
    float v2 = __uint_as_float(r2), v3 = __uint_as_float(r3);
    float v4 = __uint_as_float(r4), v5 = __uint_as_float(r5);
    float v6 = __uint_as_float(r6), v7 = __uint_as_float(r7);

    // Swap chunks between the two 16-lane halves: each lane now also has the
    // matching 8 floats of the OTHER row.
    float o0 = __shfl_xor_sync(0xffffffffu, v0, 16);
    float o1 = __shfl_xor_sync(0xffffffffu, v1, 16);
    float o2 = __shfl_xor_sync(0xffffffffu, v2, 16);
    float o3 = __shfl_xor_sync(0xffffffffu, v3, 16);
    float o4 = __shfl_xor_sync(0xffffffffu, v4, 16);
    float o5 = __shfl_xor_sync(0xffffffffu, v5, 16);
    float o6 = __shfl_xor_sync(0xffffffffu, v6, 16);
    float o7 = __shfl_xor_sync(0xffffffffu, v7, 16);

    float s = v0 * o0 + v1 * o1 + v2 * o2 + v3 * o3
            + v4 * o4 + v5 * o5 + v6 * o6 + v7 * o7;

    // Both halves hold identical partials per (lane&15); reduce within the
    // 16-lane group (4 butterfly steps).
    #pragma unroll
    for (int o = 8; o > 0; o >>= 1)
        s += __shfl_xor_sync(0xffffffffu, s, o);

    if (lane == 0) out[warp] = s;
}

extern "C" void kernel_launch(void* const* d_in, const int* in_sizes, int n_in,
                              void* d_out, int out_size)
{
    const void* p0 = d_in[0];
    const void* p1 = d_in[1];
    const int*   vii;
    const float* W;
    if (in_sizes[0] < in_sizes[1]) {
        vii = (const int*)p0;  W = (const float*)p1;
    } else {
        vii = (const int*)p1;  W = (const float*)p0;
    }
    float* out = (float*)d_out;

    const int threads = 256;                       // 8 warps/block
    const int blocks  = (BATCH * 32) / threads;    // 2048 blocks, exact cover
    sgns_dot_kernel<<<blocks, threads>>>(vii, W, out);
}